// round 8
// baseline (speedup 1.0000x reference)
#include <cuda_runtime.h>
#include <math.h>
#include <stdint.h>

// ---------------------------------------------------------------------------
// Problem constants
// ---------------------------------------------------------------------------
#define BATCH     2
#define SEQ       2048
#define DMODEL    4096
#define NHEADS    32
#define KVHEADS   8
#define HEADDIM   128
#define QKV_N     (DMODEL + 2 * KVHEADS * HEADDIM)   // 6144
#define TOKENS    (BATCH * SEQ)                      // 4096
#define CLIP_V    8.0f
#define INV_SQRT_D 0.08838834764831845f

// ---------------------------------------------------------------------------
// Scratch (device globals; no dynamic allocation allowed)
// ---------------------------------------------------------------------------
__device__ float g_qkv  [(size_t)TOKENS * QKV_N];
__device__ float g_q    [(size_t)BATCH * NHEADS  * SEQ * HEADDIM];
__device__ float g_k    [(size_t)BATCH * KVHEADS * SEQ * HEADDIM];
__device__ float g_vt   [(size_t)BATCH * KVHEADS * HEADDIM * SEQ];
__device__ float g_attn [(size_t)TOKENS * DMODEL];
__device__ float g_hid_r[(size_t)TOKENS * DMODEL];
__device__ float g_wq_r [(size_t)QKV_N  * DMODEL];
__device__ float g_wo_r [(size_t)DMODEL * DMODEL];

// ---------------------------------------------------------------------------
// helpers
// ---------------------------------------------------------------------------
__device__ __forceinline__ uint32_t f2tf(float x) {
    uint32_t r;
    asm("cvt.rna.tf32.f32 %0, %1;" : "=r"(r) : "f"(x));
    return r;
}
__device__ __forceinline__ float tfr(float x) { return __uint_as_float(f2tf(x)); }
__device__ __forceinline__ void mma_tf32(float* c, const uint32_t* a, const uint32_t* b) {
    asm volatile(
        "mma.sync.aligned.m16n8k8.row.col.f32.tf32.tf32.f32 "
        "{%0,%1,%2,%3}, {%4,%5,%6,%7}, {%8,%9}, {%0,%1,%2,%3};"
        : "+f"(c[0]), "+f"(c[1]), "+f"(c[2]), "+f"(c[3])
        : "r"(a[0]), "r"(a[1]), "r"(a[2]), "r"(a[3]), "r"(b[0]), "r"(b[1]));
}
__device__ __forceinline__ void cp16(uint32_t s, const void* g) {
    asm volatile("cp.async.cg.shared.global [%0], [%1], 16;" :: "r"(s), "l"(g));
}
__device__ __forceinline__ void ldsm_x4(uint32_t* r, uint32_t addr) {
    asm volatile("ldmatrix.sync.aligned.m8n8.x4.shared.b16 {%0,%1,%2,%3}, [%4];"
                 : "=r"(r[0]), "=r"(r[1]), "=r"(r[2]), "=r"(r[3]) : "r"(addr));
}

// ---------------------------------------------------------------------------
// elementwise tf32 pre-round (float4 grid-stride)
// ---------------------------------------------------------------------------
__global__ __launch_bounds__(256)
void round_tf32_kernel(const float4* __restrict__ in, float4* __restrict__ out, int n4)
{
    for (int i = blockIdx.x * blockDim.x + threadIdx.x; i < n4; i += gridDim.x * blockDim.x) {
        float4 v = in[i];
        v.x = tfr(v.x); v.y = tfr(v.y); v.z = tfr(v.z); v.w = tfr(v.w);
        out[i] = v;
    }
}

// ---------------------------------------------------------------------------
// TF32 tensor-core GEMM (unchanged from R7 — proven config)
// ---------------------------------------------------------------------------
#define BM 128
#define BN 128
#define BKg 32
#define BKP 36
#define STAGE_FLOATS (BM * BKP + BN * BKP)            // 9216
#define GEMM_SMEM_BYTES (2 * STAGE_FLOATS * 4)        // 73,728
#define EP_PITCH 36

template <bool DO_CLIP>
__global__ __launch_bounds__(256, 2)
void gemm_tf32(const float* __restrict__ A, const float* __restrict__ B,
               float* __restrict__ C, int M, int N, int K)
{
    extern __shared__ float sm[];
    const uint32_t smem_base = (uint32_t)__cvta_generic_to_shared(sm);

    const int tid = threadIdx.x;
    const int ln  = tid & 31;
    const int wid = tid >> 5;
    const int wm  = wid >> 2;
    const int wn  = wid & 3;
    const int m0  = blockIdx.y * BM;
    const int n0  = blockIdx.x * BN;

    const uint32_t a_lane = (uint32_t)(((wm * 64 + (ln & 15)) * BKP + (ln >> 4) * 4) * 4);
    const uint32_t b_lane = (uint32_t)(((wn * 32 + (ln >> 4) * 8 + (ln & 7)) * BKP
                                        + ((ln >> 3) & 1) * 4) * 4);

    const float* Abase = A + (size_t)m0 * K;
    const float* Bbase = B + (size_t)n0 * K;

    auto load_stage = [&](int kt, int s) {
        const float* Ag = Abase + kt * BKg;
        const float* Bg = Bbase + kt * BKg;
        const uint32_t sa = smem_base + (uint32_t)(s * STAGE_FLOATS) * 4u;
        const uint32_t sb = sa + BM * BKP * 4u;
        #pragma unroll
        for (int r = 0; r < 4; r++) {
            const int i   = r * 256 + tid;
            const int row = i >> 3;
            const int kc  = (i & 7) << 2;
            cp16(sa + (uint32_t)(row * BKP + kc) * 4u, Ag + (size_t)row * K + kc);
            cp16(sb + (uint32_t)(row * BKP + kc) * 4u, Bg + (size_t)row * K + kc);
        }
        asm volatile("cp.async.commit_group;");
    };

    load_stage(0, 0);

    float acc[4][4][4];
    #pragma unroll
    for (int a = 0; a < 4; a++)
        #pragma unroll
        for (int b = 0; b < 4; b++)
            #pragma unroll
            for (int c = 0; c < 4; c++) acc[a][b][c] = 0.0f;

    const int nk = K / BKg;
    for (int kt = 0; kt < nk; kt++) {
        if (kt + 1 < nk) {
            load_stage(kt + 1, (kt + 1) & 1);
            asm volatile("cp.async.wait_group 1;");
        } else {
            asm volatile("cp.async.wait_group 0;");
        }
        __syncthreads();

        const uint32_t as_s = smem_base + (uint32_t)((kt & 1) * STAGE_FLOATS) * 4u;
        const uint32_t aa = as_s + a_lane;
        const uint32_t bb = as_s + BM * BKP * 4u + b_lane;

        #pragma unroll
        for (int ks = 0; ks < 4; ks++) {
            const uint32_t k0b = (uint32_t)(ks * 8 * 4);
            uint32_t af[4][4], bf[2][4];
            #pragma unroll
            for (int mt = 0; mt < 4; mt++)
                ldsm_x4(af[mt], aa + (uint32_t)(mt * 16 * BKP * 4) + k0b);
            ldsm_x4(bf[0], bb + k0b);
            ldsm_x4(bf[1], bb + (uint32_t)(16 * BKP * 4) + k0b);
            #pragma unroll
            for (int mt = 0; mt < 4; mt++) {
                mma_tf32(acc[mt][0], af[mt], &bf[0][0]);
                mma_tf32(acc[mt][1], af[mt], &bf[0][2]);
                mma_tf32(acc[mt][2], af[mt], &bf[1][0]);
                mma_tf32(acc[mt][3], af[mt], &bf[1][2]);
            }
        }
        __syncthreads();
    }

    float* ep = sm + wid * (64 * EP_PITCH);
    #pragma unroll
    for (int mt = 0; mt < 4; mt++) {
        __syncwarp();
        const int lq = ln >> 2, lr = ln & 3;
        #pragma unroll
        for (int nt = 0; nt < 4; nt++) {
            float* p0 = ep + (lq)     * EP_PITCH + nt * 8 + lr * 2;
            float* p1 = ep + (lq + 8) * EP_PITCH + nt * 8 + lr * 2;
            p0[0] = acc[mt][nt][0]; p0[1] = acc[mt][nt][1];
            p1[0] = acc[mt][nt][2]; p1[1] = acc[mt][nt][3];
        }
        __syncwarp();
        #pragma unroll
        for (int rr = 0; rr < 4; rr++) {
            const int row = rr * 4 + (ln >> 3);
            const int c4  = (ln & 7) * 4;
            float4 v = *(float4*)&ep[row * EP_PITCH + c4];
            if (DO_CLIP) {
                v.x = fminf(fmaxf(v.x, -CLIP_V), CLIP_V);
                v.y = fminf(fmaxf(v.y, -CLIP_V), CLIP_V);
                v.z = fminf(fmaxf(v.z, -CLIP_V), CLIP_V);
                v.w = fminf(fmaxf(v.w, -CLIP_V), CLIP_V);
            }
            *(float4*)(C + (size_t)(m0 + wm * 64 + mt * 16 + row) * N
                         + n0 + wn * 32 + c4) = v;
        }
    }
}

// ---------------------------------------------------------------------------
// RoPE + layout
// ---------------------------------------------------------------------------
__global__ __launch_bounds__(256)
void rope_kernel()
{
    const int token = blockIdx.x;
    const int b    = token / SEQ;
    const int spos = token - b * SEQ;
    const float* row = g_qkv + (size_t)token * QKV_N;
    const float posf = (float)spos;

    for (int idx = threadIdx.x; idx < (NHEADS + KVHEADS) * 64; idx += 256) {
        const int h = idx >> 6;
        const int j = idx & 63;
        const float freq = __powf(500000.0f, -(float)j * (1.0f / 64.0f));
        float s, c;
        sincosf(posf * freq, &s, &c);

        const float x1 = row[h * HEADDIM + j];
        const float x2 = row[h * HEADDIM + 64 + j];
        const float y1 = x1 * c - x2 * s;
        const float y2 = x2 * c + x1 * s;

        if (h < NHEADS) {
            float* q = g_q + ((size_t)(b * NHEADS + h) * SEQ + spos) * HEADDIM;
            q[j]      = tfr(y1 * INV_SQRT_D);
            q[j + 64] = tfr(y2 * INV_SQRT_D);
        } else {
            float* k = g_k + ((size_t)(b * KVHEADS + (h - NHEADS)) * SEQ + spos) * HEADDIM;
            k[j]      = tfr(y1);
            k[j + 64] = tfr(y2);
        }
    }

    const float* vrow = row + DMODEL + KVHEADS * HEADDIM;
    for (int idx = threadIdx.x; idx < KVHEADS * HEADDIM; idx += 256) {
        const int hk = idx >> 7;
        const int d  = idx & 127;
        g_vt[((size_t)(b * KVHEADS + hk) * HEADDIM + d) * SEQ + spos] = tfr(vrow[hk * HEADDIM + d]);
    }
}

// ---------------------------------------------------------------------------
// Tensor-core causal flash attention — Q fragments in registers,
// K prefetch hidden behind softmax+PV, heavy tiles scheduled first.
// smem: Ks[64][132] (also Q staging), Ps[64][68], Vt[128][68] = 86,016 B.
// ---------------------------------------------------------------------------
#define K_PITCH 132
#define P_PITCH 68
#define V_PITCH 68
#define ATTN_SMEM_FLOATS (64 * K_PITCH + 64 * P_PITCH + 128 * V_PITCH)
#define ATTN_SMEM_BYTES  (ATTN_SMEM_FLOATS * 4)   // 86,016

__global__ __launch_bounds__(128, 2)
void attn_kernel()
{
    extern __shared__ float sm[];
    float* Ps = sm + 64 * K_PITCH;
    const uint32_t smem_base = (uint32_t)__cvta_generic_to_shared(sm);
    const uint32_t ks_base = smem_base;
    const uint32_t ps_base = smem_base + 64 * K_PITCH * 4u;
    const uint32_t vt_base = ps_base + 64 * P_PITCH * 4u;

    const int qt = (SEQ / 64 - 1) - blockIdx.x;   // heavy tiles first
    const int h  = blockIdx.y;
    const int b  = blockIdx.z;
    const int hk = h >> 2;
    const int q0 = qt * 64;

    const int tid = threadIdx.x;
    const int ln  = tid & 31;
    const int wid = tid >> 5;
    const int lq  = ln >> 2;
    const int lr  = ln & 3;

    const uint32_t a_lane_k = (uint32_t)(((wid * 16 + (ln & 15)) * K_PITCH
                                          + (ln >> 4) * 4) * 4);
    const uint32_t a_lane_p = (uint32_t)(((wid * 16 + (ln & 15)) * P_PITCH
                                          + (ln >> 4) * 4) * 4);
    const uint32_t b_lane_k = (uint32_t)((((ln >> 4) * 8 + (ln & 7)) * K_PITCH
                                          + ((ln >> 3) & 1) * 4) * 4);
    const uint32_t b_lane_v = (uint32_t)((((ln >> 4) * 8 + (ln & 7)) * V_PITCH
                                          + ((ln >> 3) & 1) * 4) * 4);

    const float* Qg = g_q  + ((size_t)(b * NHEADS  + h)  * SEQ + q0) * HEADDIM;
    const float* Kg = g_k  + ((size_t)(b * KVHEADS + hk) * SEQ) * HEADDIM;
    const float* Vg = g_vt + ((size_t)(b * KVHEADS + hk) * HEADDIM) * SEQ;

    auto load_k = [&](int j0) {
        for (int i = tid; i < 2048; i += 128) {
            const int r  = i >> 5;
            const int c4 = (i & 31) << 2;
            cp16(ks_base + (uint32_t)(r * K_PITCH + c4) * 4u,
                 Kg + (size_t)(j0 + r) * HEADDIM + c4);
        }
        asm volatile("cp.async.commit_group;");
    };
    auto load_v = [&](int j0) {
        for (int i = tid; i < 2048; i += 128) {
            const int r  = i >> 4;
            const int c4 = (i & 15) << 2;
            cp16(vt_base + (uint32_t)(r * V_PITCH + c4) * 4u,
                 Vg + (size_t)r * SEQ + j0 + c4);
        }
        asm volatile("cp.async.commit_group;");
    };

    // ---- prologue: stage Q through Ks buffer, hoist fragments to registers
    for (int i = tid; i < 2048; i += 128) {
        const int r  = i >> 5;
        const int c4 = (i & 31) << 2;
        cp16(ks_base + (uint32_t)(r * K_PITCH + c4) * 4u, Qg + (size_t)r * HEADDIM + c4);
    }
    asm volatile("cp.async.commit_group;");
    asm volatile("cp.async.wait_group 0;");
    __syncthreads();

    uint32_t qf[16][4];
    #pragma unroll
    for (int ks = 0; ks < 16; ks++)
        ldsm_x4(qf[ks], ks_base + a_lane_k + (uint32_t)(ks * 8 * 4));
    __syncthreads();          // all warps done reading Q from Ks

    load_k(0);
    load_v(0);

    float m0 = -3.0e38f, m1 = -3.0e38f, l0 = 0.0f, l1 = 0.0f;
    float o[16][4];
    #pragma unroll
    for (int nt = 0; nt < 16; nt++)
        #pragma unroll
        for (int c = 0; c < 4; c++) o[nt][c] = 0.0f;

    for (int jt = 0; jt <= qt; jt++) {
        asm volatile("cp.async.wait_group 0;");
        __syncthreads();      // K(jt), V(jt) resident; Vt free from prev PV

        // ---- S = Q K^T (Q from registers) ----
        float s_[8][4];
        #pragma unroll
        for (int t = 0; t < 8; t++)
            #pragma unroll
            for (int c = 0; c < 4; c++) s_[t][c] = 0.0f;

        #pragma unroll
        for (int ks = 0; ks < 16; ks++) {
            const uint32_t k0b = (uint32_t)(ks * 8 * 4);
            #pragma unroll
            for (int p = 0; p < 4; p++) {
                uint32_t bt[4];
                ldsm_x4(bt, ks_base + b_lane_k + (uint32_t)(p * 16 * K_PITCH * 4) + k0b);
                mma_tf32(s_[2 * p],     qf[ks], &bt[0]);
                mma_tf32(s_[2 * p + 1], qf[ks], &bt[2]);
            }
        }
        __syncthreads();      // Ks consumed -> safe to overwrite

        if (jt < qt) load_k((jt + 1) * 64);   // hidden behind softmax + PV

        if (jt == qt) {       // causal mask on diagonal tile
            const int r0 = wid * 16 + lq;
            #pragma unroll
            for (int t = 0; t < 8; t++) {
                const int c0 = t * 8 + 2 * lr;
                if (c0     > r0)     s_[t][0] = -3.0e38f;
                if (c0 + 1 > r0)     s_[t][1] = -3.0e38f;
                if (c0     > r0 + 8) s_[t][2] = -3.0e38f;
                if (c0 + 1 > r0 + 8) s_[t][3] = -3.0e38f;
            }
        }

        // ---- online softmax ----
        float mx0 = -3.0e38f, mx1 = -3.0e38f;
        #pragma unroll
        for (int t = 0; t < 8; t++) {
            mx0 = fmaxf(mx0, fmaxf(s_[t][0], s_[t][1]));
            mx1 = fmaxf(mx1, fmaxf(s_[t][2], s_[t][3]));
        }
        mx0 = fmaxf(mx0, __shfl_xor_sync(0xffffffffu, mx0, 1));
        mx0 = fmaxf(mx0, __shfl_xor_sync(0xffffffffu, mx0, 2));
        mx1 = fmaxf(mx1, __shfl_xor_sync(0xffffffffu, mx1, 1));
        mx1 = fmaxf(mx1, __shfl_xor_sync(0xffffffffu, mx1, 2));

        const float mn0 = fmaxf(m0, mx0);
        const float mn1 = fmaxf(m1, mx1);
        const float al0 = __expf(m0 - mn0);
        const float al1 = __expf(m1 - mn1);
        float rs0 = 0.0f, rs1 = 0.0f;
        #pragma unroll
        for (int t = 0; t < 8; t++) {
            s_[t][0] = __expf(s_[t][0] - mn0); rs0 += s_[t][0];
            s_[t][1] = __expf(s_[t][1] - mn0); rs0 += s_[t][1];
            s_[t][2] = __expf(s_[t][2] - mn1); rs1 += s_[t][2];
            s_[t][3] = __expf(s_[t][3] - mn1); rs1 += s_[t][3];
        }
        rs0 += __shfl_xor_sync(0xffffffffu, rs0, 1);
        rs0 += __shfl_xor_sync(0xffffffffu, rs0, 2);
        rs1 += __shfl_xor_sync(0xffffffffu, rs1, 1);
        rs1 += __shfl_xor_sync(0xffffffffu, rs1, 2);
        l0 = l0 * al0 + rs0;  m0 = mn0;
        l1 = l1 * al1 + rs1;  m1 = mn1;
        #pragma unroll
        for (int nt = 0; nt < 16; nt++) {
            o[nt][0] *= al0; o[nt][1] *= al0;
            o[nt][2] *= al1; o[nt][3] *= al1;
        }

        // ---- store P (own rows only -> warp-local visibility suffices) ----
        {
            float* p0 = Ps + (wid * 16 + lq) * P_PITCH + 2 * lr;
            float* p1 = p0 + 8 * P_PITCH;
            #pragma unroll
            for (int t = 0; t < 8; t++) {
                p0[t * 8]     = tfr(s_[t][0]);
                p0[t * 8 + 1] = tfr(s_[t][1]);
                p1[t * 8]     = tfr(s_[t][2]);
                p1[t * 8 + 1] = tfr(s_[t][3]);
            }
        }
        __syncwarp();

        // ---- O += P Vt ----
        #pragma unroll
        for (int k0 = 0; k0 < 64; k0 += 8) {
            const uint32_t k0b = (uint32_t)(k0 * 4);
            uint32_t a[4];
            ldsm_x4(a, ps_base + a_lane_p + k0b);
            #pragma unroll
            for (int p = 0; p < 8; p++) {
                uint32_t bt[4];
                ldsm_x4(bt, vt_base + b_lane_v + (uint32_t)(p * 16 * V_PITCH * 4) + k0b);
                mma_tf32(o[2 * p],     a, &bt[0]);
                mma_tf32(o[2 * p + 1], a, &bt[2]);
            }
        }

        if (jt < qt) {
            __syncthreads();              // Vt consumed by all warps
            load_v((jt + 1) * 64);
        }
    }

    // ---- epilogue ----
    const float inv0 = 1.0f / l0;
    const float inv1 = 1.0f / l1;
    const int s0 = q0 + wid * 16 + lq;
    float* O0 = g_attn + (size_t)(b * SEQ + s0) * DMODEL + h * HEADDIM + 2 * lr;
    float* O1 = O0 + (size_t)8 * DMODEL;
    #pragma unroll
    for (int nt = 0; nt < 16; nt++) {
        float2 v0 = make_float2(tfr(o[nt][0] * inv0), tfr(o[nt][1] * inv0));
        float2 v1 = make_float2(tfr(o[nt][2] * inv1), tfr(o[nt][3] * inv1));
        *(float2*)(O0 + nt * 8) = v0;
        *(float2*)(O1 + nt * 8) = v1;
    }
}

// ---------------------------------------------------------------------------
// Launch sequence
// ---------------------------------------------------------------------------
extern "C" void kernel_launch(void* const* d_in, const int* in_sizes, int n_in,
                              void* d_out, int out_size)
{
    const float* hidden = (const float*)d_in[0];
    const float* Wqkv   = (const float*)d_in[3];
    const float* out_w  = (const float*)d_in[4];
    float*       out    = (float*)d_out;

    float *qkv_p, *attn_p, *hid_p, *wq_p, *wo_p;
    cudaGetSymbolAddress((void**)&qkv_p,  g_qkv);
    cudaGetSymbolAddress((void**)&attn_p, g_attn);
    cudaGetSymbolAddress((void**)&hid_p,  g_hid_r);
    cudaGetSymbolAddress((void**)&wq_p,   g_wq_r);
    cudaGetSymbolAddress((void**)&wo_p,   g_wo_r);

    cudaFuncSetAttribute(gemm_tf32<true>,
                         cudaFuncAttributeMaxDynamicSharedMemorySize, GEMM_SMEM_BYTES);
    cudaFuncSetAttribute(gemm_tf32<false>,
                         cudaFuncAttributeMaxDynamicSharedMemorySize, GEMM_SMEM_BYTES);
    cudaFuncSetAttribute(attn_kernel,
                         cudaFuncAttributeMaxDynamicSharedMemorySize, ATTN_SMEM_BYTES);

    // 0) pre-round operands to tf32
    round_tf32_kernel<<<1184, 256>>>((const float4*)hidden, (float4*)hid_p,
                                     TOKENS * DMODEL / 4);
    round_tf32_kernel<<<1184, 256>>>((const float4*)Wqkv, (float4*)wq_p,
                                     QKV_N * DMODEL / 4);
    round_tf32_kernel<<<1184, 256>>>((const float4*)out_w, (float4*)wo_p,
                                     DMODEL * DMODEL / 4);

    // 1) QKV projection with clip
    gemm_tf32<true><<<dim3(QKV_N / BN, TOKENS / BM), 256, GEMM_SMEM_BYTES>>>(
        hid_p, wq_p, qkv_p, TOKENS, QKV_N, DMODEL);

    // 2) RoPE + layouts (tf32-rounded outputs)
    rope_kernel<<<TOKENS, 256>>>();

    // 3) tensor-core causal flash attention
    attn_kernel<<<dim3(SEQ / 64, NHEADS, BATCH), 128, ATTN_SMEM_BYTES>>>();

    // 4) output projection
    gemm_tf32<false><<<dim3(DMODEL / BN, TOKENS / BM), 256, GEMM_SMEM_BYTES>>>(
        attn_p, wo_p, out, TOKENS, DMODEL, DMODEL);
}

// round 9
// speedup vs baseline: 1.0099x; 1.0099x over previous
#include <cuda_runtime.h>
#include <math.h>
#include <stdint.h>

// ---------------------------------------------------------------------------
// Problem constants
// ---------------------------------------------------------------------------
#define BATCH     2
#define SEQ       2048
#define DMODEL    4096
#define NHEADS    32
#define KVHEADS   8
#define HEADDIM   128
#define QKV_N     (DMODEL + 2 * KVHEADS * HEADDIM)   // 6144
#define TOKENS    (BATCH * SEQ)                      // 4096
#define CLIP_V    8.0f
#define INV_SQRT_D 0.08838834764831845f

// ---------------------------------------------------------------------------
// Scratch (device globals; no dynamic allocation allowed)
// ---------------------------------------------------------------------------
__device__ float g_qkv  [(size_t)TOKENS * QKV_N];
__device__ float g_q    [(size_t)BATCH * NHEADS  * SEQ * HEADDIM];
__device__ float g_k    [(size_t)BATCH * KVHEADS * SEQ * HEADDIM];
__device__ float g_vt   [(size_t)BATCH * KVHEADS * HEADDIM * SEQ];
__device__ float g_attn [(size_t)TOKENS * DMODEL];
__device__ float g_hid_r[(size_t)TOKENS * DMODEL];
__device__ float g_wq_r [(size_t)QKV_N  * DMODEL];
__device__ float g_wo_r [(size_t)DMODEL * DMODEL];

// ---------------------------------------------------------------------------
// helpers
// ---------------------------------------------------------------------------
__device__ __forceinline__ uint32_t f2tf(float x) {
    uint32_t r;
    asm("cvt.rna.tf32.f32 %0, %1;" : "=r"(r) : "f"(x));
    return r;
}
__device__ __forceinline__ float tfr(float x) { return __uint_as_float(f2tf(x)); }
__device__ __forceinline__ void mma_tf32(float* c, const uint32_t* a, const uint32_t* b) {
    asm volatile(
        "mma.sync.aligned.m16n8k8.row.col.f32.tf32.tf32.f32 "
        "{%0,%1,%2,%3}, {%4,%5,%6,%7}, {%8,%9}, {%0,%1,%2,%3};"
        : "+f"(c[0]), "+f"(c[1]), "+f"(c[2]), "+f"(c[3])
        : "r"(a[0]), "r"(a[1]), "r"(a[2]), "r"(a[3]), "r"(b[0]), "r"(b[1]));
}
__device__ __forceinline__ void cp16(uint32_t s, const void* g) {
    asm volatile("cp.async.cg.shared.global [%0], [%1], 16;" :: "r"(s), "l"(g));
}
__device__ __forceinline__ void ldsm_x4(uint32_t* r, uint32_t addr) {
    asm volatile("ldmatrix.sync.aligned.m8n8.x4.shared.b16 {%0,%1,%2,%3}, [%4];"
                 : "=r"(r[0]), "=r"(r[1]), "=r"(r[2]), "=r"(r[3]) : "r"(addr));
}

// ---------------------------------------------------------------------------
// elementwise tf32 pre-round (float4 grid-stride)
// ---------------------------------------------------------------------------
__global__ __launch_bounds__(256)
void round_tf32_kernel(const float4* __restrict__ in, float4* __restrict__ out, int n4)
{
    for (int i = blockIdx.x * blockDim.x + threadIdx.x; i < n4; i += gridDim.x * blockDim.x) {
        float4 v = in[i];
        v.x = tfr(v.x); v.y = tfr(v.y); v.z = tfr(v.z); v.w = tfr(v.w);
        out[i] = v;
    }
}

// ---------------------------------------------------------------------------
// TF32 tensor-core GEMM:  C[M,N] = A[M,K] * B[N,K]^T  (operands pre-rounded)
// 128x128x32 block tile, 8 warps (2x4), warp tile 64x32.
// 3-stage cp.async pipeline, ONE __syncthreads per mainloop iteration.
// smem 110.6KB/CTA; 2 CTAs/SM (221KB <= 228KB smem/SM, regs 128 = 64K cap).
// ldmatrix fragment feeding (pitch 36 -> conflict-free).
// ---------------------------------------------------------------------------
#define BM 128
#define BN 128
#define BKg 32
#define BKP 36
#define STAGES 3
#define STAGE_FLOATS (BM * BKP + BN * BKP)            // 9216
#define GEMM_SMEM_BYTES (STAGES * STAGE_FLOATS * 4)   // 110,592
#define EP_PITCH 36

template <bool DO_CLIP>
__global__ __launch_bounds__(256, 2)
void gemm_tf32(const float* __restrict__ A, const float* __restrict__ B,
               float* __restrict__ C, int M, int N, int K)
{
    extern __shared__ float sm[];
    const uint32_t smem_base = (uint32_t)__cvta_generic_to_shared(sm);

    const int tid = threadIdx.x;
    const int ln  = tid & 31;
    const int wid = tid >> 5;
    const int wm  = wid >> 2;
    const int wn  = wid & 3;
    const int m0  = blockIdx.y * BM;
    const int n0  = blockIdx.x * BN;

    const uint32_t a_lane = (uint32_t)(((wm * 64 + (ln & 15)) * BKP + (ln >> 4) * 4) * 4);
    const uint32_t b_lane = (uint32_t)(((wn * 32 + (ln >> 4) * 8 + (ln & 7)) * BKP
                                        + ((ln >> 3) & 1) * 4) * 4);

    const float* Abase = A + (size_t)m0 * K;
    const float* Bbase = B + (size_t)n0 * K;

    auto load_stage = [&](int kt, int s) {
        const float* Ag = Abase + kt * BKg;
        const float* Bg = Bbase + kt * BKg;
        const uint32_t sa = smem_base + (uint32_t)(s * STAGE_FLOATS) * 4u;
        const uint32_t sb = sa + BM * BKP * 4u;
        #pragma unroll
        for (int r = 0; r < 4; r++) {
            const int i   = r * 256 + tid;
            const int row = i >> 3;
            const int kc  = (i & 7) << 2;
            cp16(sa + (uint32_t)(row * BKP + kc) * 4u, Ag + (size_t)row * K + kc);
            cp16(sb + (uint32_t)(row * BKP + kc) * 4u, Bg + (size_t)row * K + kc);
        }
        asm volatile("cp.async.commit_group;");
    };

    // prologue: stages 0 and 1 in flight
    load_stage(0, 0);
    load_stage(1, 1);

    float acc[4][4][4];
    #pragma unroll
    for (int a = 0; a < 4; a++)
        #pragma unroll
        for (int b = 0; b < 4; b++)
            #pragma unroll
            for (int c = 0; c < 4; c++) acc[a][b][c] = 0.0f;

    const int nk = K / BKg;
    for (int kt = 0; kt < nk; kt++) {
        // stage kt ready when all but the most recent commit have completed
        asm volatile("cp.async.wait_group 1;");
        __syncthreads();   // also: all warps done reading buffer (kt-1)%3

        // issue next load immediately (overlaps with compute below)
        if (kt + 2 < nk) load_stage(kt + 2, (kt + 2) % STAGES);
        else             asm volatile("cp.async.commit_group;");  // keep count

        const uint32_t as_s = smem_base + (uint32_t)((kt % STAGES) * STAGE_FLOATS) * 4u;
        const uint32_t aa = as_s + a_lane;
        const uint32_t bb = as_s + BM * BKP * 4u + b_lane;

        #pragma unroll
        for (int ks = 0; ks < 4; ks++) {
            const uint32_t k0b = (uint32_t)(ks * 8 * 4);
            uint32_t af[4][4], bf[2][4];
            #pragma unroll
            for (int mt = 0; mt < 4; mt++)
                ldsm_x4(af[mt], aa + (uint32_t)(mt * 16 * BKP * 4) + k0b);
            ldsm_x4(bf[0], bb + k0b);
            ldsm_x4(bf[1], bb + (uint32_t)(16 * BKP * 4) + k0b);
            #pragma unroll
            for (int mt = 0; mt < 4; mt++) {
                mma_tf32(acc[mt][0], af[mt], &bf[0][0]);
                mma_tf32(acc[mt][1], af[mt], &bf[0][2]);
                mma_tf32(acc[mt][2], af[mt], &bf[1][0]);
                mma_tf32(acc[mt][3], af[mt], &bf[1][2]);
            }
        }
    }
    __syncthreads();   // all compute done before epilogue reuses smem

    // --- epilogue via smem (pitch 36: 144B rows, float4-aligned) ---
    float* ep = sm + wid * (64 * EP_PITCH);
    #pragma unroll
    for (int mt = 0; mt < 4; mt++) {
        __syncwarp();
        const int lq = ln >> 2, lr = ln & 3;
        #pragma unroll
        for (int nt = 0; nt < 4; nt++) {
            float* p0 = ep + (lq)     * EP_PITCH + nt * 8 + lr * 2;
            float* p1 = ep + (lq + 8) * EP_PITCH + nt * 8 + lr * 2;
            p0[0] = acc[mt][nt][0]; p0[1] = acc[mt][nt][1];
            p1[0] = acc[mt][nt][2]; p1[1] = acc[mt][nt][3];
        }
        __syncwarp();
        #pragma unroll
        for (int rr = 0; rr < 4; rr++) {
            const int row = rr * 4 + (ln >> 3);
            const int c4  = (ln & 7) * 4;
            float4 v = *(float4*)&ep[row * EP_PITCH + c4];
            if (DO_CLIP) {
                v.x = fminf(fmaxf(v.x, -CLIP_V), CLIP_V);
                v.y = fminf(fmaxf(v.y, -CLIP_V), CLIP_V);
                v.z = fminf(fmaxf(v.z, -CLIP_V), CLIP_V);
                v.w = fminf(fmaxf(v.w, -CLIP_V), CLIP_V);
            }
            *(float4*)(C + (size_t)(m0 + wm * 64 + mt * 16 + row) * N
                         + n0 + wn * 32 + c4) = v;
        }
    }
}

// ---------------------------------------------------------------------------
// RoPE + layout
// ---------------------------------------------------------------------------
__global__ __launch_bounds__(256)
void rope_kernel()
{
    const int token = blockIdx.x;
    const int b    = token / SEQ;
    const int spos = token - b * SEQ;
    const float* row = g_qkv + (size_t)token * QKV_N;
    const float posf = (float)spos;

    for (int idx = threadIdx.x; idx < (NHEADS + KVHEADS) * 64; idx += 256) {
        const int h = idx >> 6;
        const int j = idx & 63;
        const float freq = __powf(500000.0f, -(float)j * (1.0f / 64.0f));
        float s, c;
        sincosf(posf * freq, &s, &c);

        const float x1 = row[h * HEADDIM + j];
        const float x2 = row[h * HEADDIM + 64 + j];
        const float y1 = x1 * c - x2 * s;
        const float y2 = x2 * c + x1 * s;

        if (h < NHEADS) {
            float* q = g_q + ((size_t)(b * NHEADS + h) * SEQ + spos) * HEADDIM;
            q[j]      = tfr(y1 * INV_SQRT_D);
            q[j + 64] = tfr(y2 * INV_SQRT_D);
        } else {
            float* k = g_k + ((size_t)(b * KVHEADS + (h - NHEADS)) * SEQ + spos) * HEADDIM;
            k[j]      = tfr(y1);
            k[j + 64] = tfr(y2);
        }
    }

    const float* vrow = row + DMODEL + KVHEADS * HEADDIM;
    for (int idx = threadIdx.x; idx < KVHEADS * HEADDIM; idx += 256) {
        const int hk = idx >> 7;
        const int d  = idx & 127;
        g_vt[((size_t)(b * KVHEADS + hk) * HEADDIM + d) * SEQ + spos] = tfr(vrow[hk * HEADDIM + d]);
    }
}

// ---------------------------------------------------------------------------
// Tensor-core causal flash attention — Q fragments in registers,
// K prefetch hidden behind softmax+PV, heavy tiles scheduled first.
// smem: Ks[64][132] (also Q staging), Ps[64][68], Vt[128][68] = 86,016 B.
// ---------------------------------------------------------------------------
#define K_PITCH 132
#define P_PITCH 68
#define V_PITCH 68
#define ATTN_SMEM_FLOATS (64 * K_PITCH + 64 * P_PITCH + 128 * V_PITCH)
#define ATTN_SMEM_BYTES  (ATTN_SMEM_FLOATS * 4)   // 86,016

__global__ __launch_bounds__(128, 2)
void attn_kernel()
{
    extern __shared__ float sm[];
    float* Ps = sm + 64 * K_PITCH;
    const uint32_t smem_base = (uint32_t)__cvta_generic_to_shared(sm);
    const uint32_t ks_base = smem_base;
    const uint32_t ps_base = smem_base + 64 * K_PITCH * 4u;
    const uint32_t vt_base = ps_base + 64 * P_PITCH * 4u;

    const int qt = (SEQ / 64 - 1) - blockIdx.x;   // heavy tiles first
    const int h  = blockIdx.y;
    const int b  = blockIdx.z;
    const int hk = h >> 2;
    const int q0 = qt * 64;

    const int tid = threadIdx.x;
    const int ln  = tid & 31;
    const int wid = tid >> 5;
    const int lq  = ln >> 2;
    const int lr  = ln & 3;

    const uint32_t a_lane_k = (uint32_t)(((wid * 16 + (ln & 15)) * K_PITCH
                                          + (ln >> 4) * 4) * 4);
    const uint32_t a_lane_p = (uint32_t)(((wid * 16 + (ln & 15)) * P_PITCH
                                          + (ln >> 4) * 4) * 4);
    const uint32_t b_lane_k = (uint32_t)((((ln >> 4) * 8 + (ln & 7)) * K_PITCH
                                          + ((ln >> 3) & 1) * 4) * 4);
    const uint32_t b_lane_v = (uint32_t)((((ln >> 4) * 8 + (ln & 7)) * V_PITCH
                                          + ((ln >> 3) & 1) * 4) * 4);

    const float* Qg = g_q  + ((size_t)(b * NHEADS  + h)  * SEQ + q0) * HEADDIM;
    const float* Kg = g_k  + ((size_t)(b * KVHEADS + hk) * SEQ) * HEADDIM;
    const float* Vg = g_vt + ((size_t)(b * KVHEADS + hk) * HEADDIM) * SEQ;

    auto load_k = [&](int j0) {
        for (int i = tid; i < 2048; i += 128) {
            const int r  = i >> 5;
            const int c4 = (i & 31) << 2;
            cp16(ks_base + (uint32_t)(r * K_PITCH + c4) * 4u,
                 Kg + (size_t)(j0 + r) * HEADDIM + c4);
        }
        asm volatile("cp.async.commit_group;");
    };
    auto load_v = [&](int j0) {
        for (int i = tid; i < 2048; i += 128) {
            const int r  = i >> 4;
            const int c4 = (i & 15) << 2;
            cp16(vt_base + (uint32_t)(r * V_PITCH + c4) * 4u,
                 Vg + (size_t)r * SEQ + j0 + c4);
        }
        asm volatile("cp.async.commit_group;");
    };

    // ---- prologue: stage Q through Ks buffer, hoist fragments to registers
    for (int i = tid; i < 2048; i += 128) {
        const int r  = i >> 5;
        const int c4 = (i & 31) << 2;
        cp16(ks_base + (uint32_t)(r * K_PITCH + c4) * 4u, Qg + (size_t)r * HEADDIM + c4);
    }
    asm volatile("cp.async.commit_group;");
    asm volatile("cp.async.wait_group 0;");
    __syncthreads();

    uint32_t qf[16][4];
    #pragma unroll
    for (int ks = 0; ks < 16; ks++)
        ldsm_x4(qf[ks], ks_base + a_lane_k + (uint32_t)(ks * 8 * 4));
    __syncthreads();

    load_k(0);
    load_v(0);

    float m0 = -3.0e38f, m1 = -3.0e38f, l0 = 0.0f, l1 = 0.0f;
    float o[16][4];
    #pragma unroll
    for (int nt = 0; nt < 16; nt++)
        #pragma unroll
        for (int c = 0; c < 4; c++) o[nt][c] = 0.0f;

    for (int jt = 0; jt <= qt; jt++) {
        asm volatile("cp.async.wait_group 0;");
        __syncthreads();

        // ---- S = Q K^T (Q from registers) ----
        float s_[8][4];
        #pragma unroll
        for (int t = 0; t < 8; t++)
            #pragma unroll
            for (int c = 0; c < 4; c++) s_[t][c] = 0.0f;

        #pragma unroll
        for (int ks = 0; ks < 16; ks++) {
            const uint32_t k0b = (uint32_t)(ks * 8 * 4);
            #pragma unroll
            for (int p = 0; p < 4; p++) {
                uint32_t bt[4];
                ldsm_x4(bt, ks_base + b_lane_k + (uint32_t)(p * 16 * K_PITCH * 4) + k0b);
                mma_tf32(s_[2 * p],     qf[ks], &bt[0]);
                mma_tf32(s_[2 * p + 1], qf[ks], &bt[2]);
            }
        }
        __syncthreads();

        if (jt < qt) load_k((jt + 1) * 64);

        if (jt == qt) {
            const int r0 = wid * 16 + lq;
            #pragma unroll
            for (int t = 0; t < 8; t++) {
                const int c0 = t * 8 + 2 * lr;
                if (c0     > r0)     s_[t][0] = -3.0e38f;
                if (c0 + 1 > r0)     s_[t][1] = -3.0e38f;
                if (c0     > r0 + 8) s_[t][2] = -3.0e38f;
                if (c0 + 1 > r0 + 8) s_[t][3] = -3.0e38f;
            }
        }

        // ---- online softmax ----
        float mx0 = -3.0e38f, mx1 = -3.0e38f;
        #pragma unroll
        for (int t = 0; t < 8; t++) {
            mx0 = fmaxf(mx0, fmaxf(s_[t][0], s_[t][1]));
            mx1 = fmaxf(mx1, fmaxf(s_[t][2], s_[t][3]));
        }
        mx0 = fmaxf(mx0, __shfl_xor_sync(0xffffffffu, mx0, 1));
        mx0 = fmaxf(mx0, __shfl_xor_sync(0xffffffffu, mx0, 2));
        mx1 = fmaxf(mx1, __shfl_xor_sync(0xffffffffu, mx1, 1));
        mx1 = fmaxf(mx1, __shfl_xor_sync(0xffffffffu, mx1, 2));

        const float mn0 = fmaxf(m0, mx0);
        const float mn1 = fmaxf(m1, mx1);
        const float al0 = __expf(m0 - mn0);
        const float al1 = __expf(m1 - mn1);
        float rs0 = 0.0f, rs1 = 0.0f;
        #pragma unroll
        for (int t = 0; t < 8; t++) {
            s_[t][0] = __expf(s_[t][0] - mn0); rs0 += s_[t][0];
            s_[t][1] = __expf(s_[t][1] - mn0); rs0 += s_[t][1];
            s_[t][2] = __expf(s_[t][2] - mn1); rs1 += s_[t][2];
            s_[t][3] = __expf(s_[t][3] - mn1); rs1 += s_[t][3];
        }
        rs0 += __shfl_xor_sync(0xffffffffu, rs0, 1);
        rs0 += __shfl_xor_sync(0xffffffffu, rs0, 2);
        rs1 += __shfl_xor_sync(0xffffffffu, rs1, 1);
        rs1 += __shfl_xor_sync(0xffffffffu, rs1, 2);
        l0 = l0 * al0 + rs0;  m0 = mn0;
        l1 = l1 * al1 + rs1;  m1 = mn1;
        #pragma unroll
        for (int nt = 0; nt < 16; nt++) {
            o[nt][0] *= al0; o[nt][1] *= al0;
            o[nt][2] *= al1; o[nt][3] *= al1;
        }

        // ---- store P (own rows only -> warp-local visibility suffices) ----
        {
            float* p0 = Ps + (wid * 16 + lq) * P_PITCH + 2 * lr;
            float* p1 = p0 + 8 * P_PITCH;
            #pragma unroll
            for (int t = 0; t < 8; t++) {
                p0[t * 8]     = tfr(s_[t][0]);
                p0[t * 8 + 1] = tfr(s_[t][1]);
                p1[t * 8]     = tfr(s_[t][2]);
                p1[t * 8 + 1] = tfr(s_[t][3]);
            }
        }
        __syncwarp();

        // ---- O += P Vt ----
        #pragma unroll
        for (int k0 = 0; k0 < 64; k0 += 8) {
            const uint32_t k0b = (uint32_t)(k0 * 4);
            uint32_t a[4];
            ldsm_x4(a, ps_base + a_lane_p + k0b);
            #pragma unroll
            for (int p = 0; p < 8; p++) {
                uint32_t bt[4];
                ldsm_x4(bt, vt_base + b_lane_v + (uint32_t)(p * 16 * V_PITCH * 4) + k0b);
                mma_tf32(o[2 * p],     a, &bt[0]);
                mma_tf32(o[2 * p + 1], a, &bt[2]);
            }
        }

        if (jt < qt) {
            __syncthreads();
            load_v((jt + 1) * 64);
        }
    }

    // ---- epilogue ----
    const float inv0 = 1.0f / l0;
    const float inv1 = 1.0f / l1;
    const int s0 = q0 + wid * 16 + lq;
    float* O0 = g_attn + (size_t)(b * SEQ + s0) * DMODEL + h * HEADDIM + 2 * lr;
    float* O1 = O0 + (size_t)8 * DMODEL;
    #pragma unroll
    for (int nt = 0; nt < 16; nt++) {
        float2 v0 = make_float2(tfr(o[nt][0] * inv0), tfr(o[nt][1] * inv0));
        float2 v1 = make_float2(tfr(o[nt][2] * inv1), tfr(o[nt][3] * inv1));
        *(float2*)(O0 + nt * 8) = v0;
        *(float2*)(O1 + nt * 8) = v1;
    }
}

// ---------------------------------------------------------------------------
// Launch sequence
// ---------------------------------------------------------------------------
extern "C" void kernel_launch(void* const* d_in, const int* in_sizes, int n_in,
                              void* d_out, int out_size)
{
    const float* hidden = (const float*)d_in[0];
    const float* Wqkv   = (const float*)d_in[3];
    const float* out_w  = (const float*)d_in[4];
    float*       out    = (float*)d_out;

    float *qkv_p, *attn_p, *hid_p, *wq_p, *wo_p;
    cudaGetSymbolAddress((void**)&qkv_p,  g_qkv);
    cudaGetSymbolAddress((void**)&attn_p, g_attn);
    cudaGetSymbolAddress((void**)&hid_p,  g_hid_r);
    cudaGetSymbolAddress((void**)&wq_p,   g_wq_r);
    cudaGetSymbolAddress((void**)&wo_p,   g_wo_r);

    cudaFuncSetAttribute(gemm_tf32<true>,
                         cudaFuncAttributeMaxDynamicSharedMemorySize, GEMM_SMEM_BYTES);
    cudaFuncSetAttribute(gemm_tf32<false>,
                         cudaFuncAttributeMaxDynamicSharedMemorySize, GEMM_SMEM_BYTES);
    cudaFuncSetAttribute(attn_kernel,
                         cudaFuncAttributeMaxDynamicSharedMemorySize, ATTN_SMEM_BYTES);

    // 0) pre-round operands to tf32
    round_tf32_kernel<<<1184, 256>>>((const float4*)hidden, (float4*)hid_p,
                                     TOKENS * DMODEL / 4);
    round_tf32_kernel<<<1184, 256>>>((const float4*)Wqkv, (float4*)wq_p,
                                     QKV_N * DMODEL / 4);
    round_tf32_kernel<<<1184, 256>>>((const float4*)out_w, (float4*)wo_p,
                                     DMODEL * DMODEL / 4);

    // 1) QKV projection with clip
    gemm_tf32<true><<<dim3(QKV_N / BN, TOKENS / BM), 256, GEMM_SMEM_BYTES>>>(
        hid_p, wq_p, qkv_p, TOKENS, QKV_N, DMODEL);

    // 2) RoPE + layouts (tf32-rounded outputs)
    rope_kernel<<<TOKENS, 256>>>();

    // 3) tensor-core causal flash attention
    attn_kernel<<<dim3(SEQ / 64, NHEADS, BATCH), 128, ATTN_SMEM_BYTES>>>();

    // 4) output projection
    gemm_tf32<false><<<dim3(DMODEL / BN, TOKENS / BM), 256, GEMM_SMEM_BYTES>>>(
        attn_p, wo_p, out, TOKENS, DMODEL, DMODEL);
}

// round 10
// speedup vs baseline: 1.0286x; 1.0185x over previous
#include <cuda_runtime.h>
#include <math.h>
#include <stdint.h>

// ---------------------------------------------------------------------------
// Problem constants
// ---------------------------------------------------------------------------
#define BATCH     2
#define SEQ       2048
#define DMODEL    4096
#define NHEADS    32
#define KVHEADS   8
#define HEADDIM   128
#define QKV_N     (DMODEL + 2 * KVHEADS * HEADDIM)   // 6144
#define TOKENS    (BATCH * SEQ)                      // 4096
#define CLIP_V    8.0f
#define INV_SQRT_D 0.08838834764831845f

// ---------------------------------------------------------------------------
// Scratch (device globals; no dynamic allocation allowed)
// ---------------------------------------------------------------------------
__device__ float g_qkv  [(size_t)TOKENS * QKV_N];
__device__ float g_q    [(size_t)BATCH * NHEADS  * SEQ * HEADDIM];
__device__ float g_k    [(size_t)BATCH * KVHEADS * SEQ * HEADDIM];
__device__ float g_vt   [(size_t)BATCH * KVHEADS * HEADDIM * SEQ];
__device__ float g_attn [(size_t)TOKENS * DMODEL];
__device__ float g_hid_r[(size_t)TOKENS * DMODEL];
__device__ float g_wq_r [(size_t)QKV_N  * DMODEL];
__device__ float g_wo_r [(size_t)DMODEL * DMODEL];

// ---------------------------------------------------------------------------
// helpers
// ---------------------------------------------------------------------------
__device__ __forceinline__ uint32_t f2tf(float x) {
    uint32_t r;
    asm("cvt.rna.tf32.f32 %0, %1;" : "=r"(r) : "f"(x));
    return r;
}
__device__ __forceinline__ float tfr(float x) { return __uint_as_float(f2tf(x)); }
__device__ __forceinline__ void mma_tf32(float* c, const uint32_t* a, const uint32_t* b) {
    asm volatile(
        "mma.sync.aligned.m16n8k8.row.col.f32.tf32.tf32.f32 "
        "{%0,%1,%2,%3}, {%4,%5,%6,%7}, {%8,%9}, {%0,%1,%2,%3};"
        : "+f"(c[0]), "+f"(c[1]), "+f"(c[2]), "+f"(c[3])
        : "r"(a[0]), "r"(a[1]), "r"(a[2]), "r"(a[3]), "r"(b[0]), "r"(b[1]));
}
__device__ __forceinline__ void cp16(uint32_t s, const void* g) {
    asm volatile("cp.async.cg.shared.global [%0], [%1], 16;" :: "r"(s), "l"(g));
}
__device__ __forceinline__ void ldsm_x4(uint32_t* r, uint32_t addr) {
    asm volatile("ldmatrix.sync.aligned.m8n8.x4.shared.b16 {%0,%1,%2,%3}, [%4];"
                 : "=r"(r[0]), "=r"(r[1]), "=r"(r[2]), "=r"(r[3]) : "r"(addr));
}

// ---------------------------------------------------------------------------
// elementwise tf32 pre-round (float4 grid-stride)
// ---------------------------------------------------------------------------
__global__ __launch_bounds__(256)
void round_tf32_kernel(const float4* __restrict__ in, float4* __restrict__ out, int n4)
{
    for (int i = blockIdx.x * blockDim.x + threadIdx.x; i < n4; i += gridDim.x * blockDim.x) {
        float4 v = in[i];
        v.x = tfr(v.x); v.y = tfr(v.y); v.z = tfr(v.z); v.w = tfr(v.w);
        out[i] = v;
    }
}

// ---------------------------------------------------------------------------
// TF32 tensor-core GEMM (unchanged from R9 — best measured config)
// ---------------------------------------------------------------------------
#define BM 128
#define BN 128
#define BKg 32
#define BKP 36
#define STAGES 3
#define STAGE_FLOATS (BM * BKP + BN * BKP)            // 9216
#define GEMM_SMEM_BYTES (STAGES * STAGE_FLOATS * 4)   // 110,592
#define EP_PITCH 36

template <bool DO_CLIP>
__global__ __launch_bounds__(256, 2)
void gemm_tf32(const float* __restrict__ A, const float* __restrict__ B,
               float* __restrict__ C, int M, int N, int K)
{
    extern __shared__ float sm[];
    const uint32_t smem_base = (uint32_t)__cvta_generic_to_shared(sm);

    const int tid = threadIdx.x;
    const int ln  = tid & 31;
    const int wid = tid >> 5;
    const int wm  = wid >> 2;
    const int wn  = wid & 3;
    const int m0  = blockIdx.y * BM;
    const int n0  = blockIdx.x * BN;

    const uint32_t a_lane = (uint32_t)(((wm * 64 + (ln & 15)) * BKP + (ln >> 4) * 4) * 4);
    const uint32_t b_lane = (uint32_t)(((wn * 32 + (ln >> 4) * 8 + (ln & 7)) * BKP
                                        + ((ln >> 3) & 1) * 4) * 4);

    const float* Abase = A + (size_t)m0 * K;
    const float* Bbase = B + (size_t)n0 * K;

    auto load_stage = [&](int kt, int s) {
        const float* Ag = Abase + kt * BKg;
        const float* Bg = Bbase + kt * BKg;
        const uint32_t sa = smem_base + (uint32_t)(s * STAGE_FLOATS) * 4u;
        const uint32_t sb = sa + BM * BKP * 4u;
        #pragma unroll
        for (int r = 0; r < 4; r++) {
            const int i   = r * 256 + tid;
            const int row = i >> 3;
            const int kc  = (i & 7) << 2;
            cp16(sa + (uint32_t)(row * BKP + kc) * 4u, Ag + (size_t)row * K + kc);
            cp16(sb + (uint32_t)(row * BKP + kc) * 4u, Bg + (size_t)row * K + kc);
        }
        asm volatile("cp.async.commit_group;");
    };

    load_stage(0, 0);
    load_stage(1, 1);

    float acc[4][4][4];
    #pragma unroll
    for (int a = 0; a < 4; a++)
        #pragma unroll
        for (int b = 0; b < 4; b++)
            #pragma unroll
            for (int c = 0; c < 4; c++) acc[a][b][c] = 0.0f;

    const int nk = K / BKg;
    for (int kt = 0; kt < nk; kt++) {
        asm volatile("cp.async.wait_group 1;");
        __syncthreads();

        if (kt + 2 < nk) load_stage(kt + 2, (kt + 2) % STAGES);
        else             asm volatile("cp.async.commit_group;");

        const uint32_t as_s = smem_base + (uint32_t)((kt % STAGES) * STAGE_FLOATS) * 4u;
        const uint32_t aa = as_s + a_lane;
        const uint32_t bb = as_s + BM * BKP * 4u + b_lane;

        #pragma unroll
        for (int ks = 0; ks < 4; ks++) {
            const uint32_t k0b = (uint32_t)(ks * 8 * 4);
            uint32_t af[4][4], bf[2][4];
            #pragma unroll
            for (int mt = 0; mt < 4; mt++)
                ldsm_x4(af[mt], aa + (uint32_t)(mt * 16 * BKP * 4) + k0b);
            ldsm_x4(bf[0], bb + k0b);
            ldsm_x4(bf[1], bb + (uint32_t)(16 * BKP * 4) + k0b);
            #pragma unroll
            for (int mt = 0; mt < 4; mt++) {
                mma_tf32(acc[mt][0], af[mt], &bf[0][0]);
                mma_tf32(acc[mt][1], af[mt], &bf[0][2]);
                mma_tf32(acc[mt][2], af[mt], &bf[1][0]);
                mma_tf32(acc[mt][3], af[mt], &bf[1][2]);
            }
        }
    }
    __syncthreads();

    float* ep = sm + wid * (64 * EP_PITCH);
    #pragma unroll
    for (int mt = 0; mt < 4; mt++) {
        __syncwarp();
        const int lq = ln >> 2, lr = ln & 3;
        #pragma unroll
        for (int nt = 0; nt < 4; nt++) {
            float* p0 = ep + (lq)     * EP_PITCH + nt * 8 + lr * 2;
            float* p1 = ep + (lq + 8) * EP_PITCH + nt * 8 + lr * 2;
            p0[0] = acc[mt][nt][0]; p0[1] = acc[mt][nt][1];
            p1[0] = acc[mt][nt][2]; p1[1] = acc[mt][nt][3];
        }
        __syncwarp();
        #pragma unroll
        for (int rr = 0; rr < 4; rr++) {
            const int row = rr * 4 + (ln >> 3);
            const int c4  = (ln & 7) * 4;
            float4 v = *(float4*)&ep[row * EP_PITCH + c4];
            if (DO_CLIP) {
                v.x = fminf(fmaxf(v.x, -CLIP_V), CLIP_V);
                v.y = fminf(fmaxf(v.y, -CLIP_V), CLIP_V);
                v.z = fminf(fmaxf(v.z, -CLIP_V), CLIP_V);
                v.w = fminf(fmaxf(v.w, -CLIP_V), CLIP_V);
            }
            *(float4*)(C + (size_t)(m0 + wm * 64 + mt * 16 + row) * N
                         + n0 + wn * 32 + c4) = v;
        }
    }
}

// ---------------------------------------------------------------------------
// RoPE + layout (unchanged)
// ---------------------------------------------------------------------------
__global__ __launch_bounds__(256)
void rope_kernel()
{
    const int token = blockIdx.x;
    const int b    = token / SEQ;
    const int spos = token - b * SEQ;
    const float* row = g_qkv + (size_t)token * QKV_N;
    const float posf = (float)spos;

    for (int idx = threadIdx.x; idx < (NHEADS + KVHEADS) * 64; idx += 256) {
        const int h = idx >> 6;
        const int j = idx & 63;
        const float freq = __powf(500000.0f, -(float)j * (1.0f / 64.0f));
        float s, c;
        sincosf(posf * freq, &s, &c);

        const float x1 = row[h * HEADDIM + j];
        const float x2 = row[h * HEADDIM + 64 + j];
        const float y1 = x1 * c - x2 * s;
        const float y2 = x2 * c + x1 * s;

        if (h < NHEADS) {
            float* q = g_q + ((size_t)(b * NHEADS + h) * SEQ + spos) * HEADDIM;
            q[j]      = tfr(y1 * INV_SQRT_D);
            q[j + 64] = tfr(y2 * INV_SQRT_D);
        } else {
            float* k = g_k + ((size_t)(b * KVHEADS + (h - NHEADS)) * SEQ + spos) * HEADDIM;
            k[j]      = tfr(y1);
            k[j + 64] = tfr(y2);
        }
    }

    const float* vrow = row + DMODEL + KVHEADS * HEADDIM;
    for (int idx = threadIdx.x; idx < KVHEADS * HEADDIM; idx += 256) {
        const int hk = idx >> 7;
        const int d  = idx & 127;
        g_vt[((size_t)(b * KVHEADS + hk) * HEADDIM + d) * SEQ + spos] = tfr(vrow[hk * HEADDIM + d]);
    }
}

// ---------------------------------------------------------------------------
// Tensor-core causal flash attention — Bq=128, 8 warps, Q in registers,
// double-buffered K and V (all steady-state loads hidden).
// smem: K0[64][132] K1[64][132] V0[128][68] V1[128][68] P[128][68] = 172,032 B
// Q staged across K0+K1 (contiguous 128x132) in the prologue.
// ---------------------------------------------------------------------------
#define K_PITCH 132
#define P_PITCH 68
#define V_PITCH 68
#define AK_BYTES (64 * K_PITCH * 4)     // one K buffer: 33,792
#define AV_BYTES (128 * V_PITCH * 4)    // one V buffer: 34,816
#define ATTN_SMEM_BYTES (2 * AK_BYTES + 2 * AV_BYTES + 128 * P_PITCH * 4) // 172,032

__global__ __launch_bounds__(256, 1)
void attn_kernel()
{
    extern __shared__ float sm[];
    const uint32_t smem_base = (uint32_t)__cvta_generic_to_shared(sm);
    const uint32_t kb[2] = { smem_base, smem_base + AK_BYTES };
    const uint32_t vb[2] = { smem_base + 2 * AK_BYTES,
                             smem_base + 2 * AK_BYTES + AV_BYTES };
    const uint32_t ps_base = smem_base + 2 * AK_BYTES + 2 * AV_BYTES;
    float* Ps = sm + (2 * AK_BYTES + 2 * AV_BYTES) / 4;

    const int qtile = (SEQ / 128 - 1) - blockIdx.x;   // heavy tiles first
    const int h  = blockIdx.y;
    const int b  = blockIdx.z;
    const int hk = h >> 2;
    const int q0 = qtile * 128;
    const int nj = 2 * qtile + 2;                     // 64-wide k-tiles

    const int tid = threadIdx.x;
    const int ln  = tid & 31;
    const int wid = tid >> 5;                         // 0..7
    const int lq  = ln >> 2;
    const int lr  = ln & 3;

    const uint32_t a_lane_k = (uint32_t)(((wid * 16 + (ln & 15)) * K_PITCH
                                          + (ln >> 4) * 4) * 4);
    const uint32_t a_lane_p = (uint32_t)(((wid * 16 + (ln & 15)) * P_PITCH
                                          + (ln >> 4) * 4) * 4);
    const uint32_t b_lane_k = (uint32_t)((((ln >> 4) * 8 + (ln & 7)) * K_PITCH
                                          + ((ln >> 3) & 1) * 4) * 4);
    const uint32_t b_lane_v = (uint32_t)((((ln >> 4) * 8 + (ln & 7)) * V_PITCH
                                          + ((ln >> 3) & 1) * 4) * 4);

    const float* Qg = g_q  + ((size_t)(b * NHEADS  + h)  * SEQ + q0) * HEADDIM;
    const float* Kg = g_k  + ((size_t)(b * KVHEADS + hk) * SEQ) * HEADDIM;
    const float* Vg = g_vt + ((size_t)(b * KVHEADS + hk) * HEADDIM) * SEQ;

    auto load_k = [&](int jt) {
        const int j0 = jt * 64;
        const uint32_t base = kb[jt & 1];
        for (int i = tid; i < 2048; i += 256) {
            const int r  = i >> 5;
            const int c4 = (i & 31) << 2;
            cp16(base + (uint32_t)(r * K_PITCH + c4) * 4u,
                 Kg + (size_t)(j0 + r) * HEADDIM + c4);
        }
        asm volatile("cp.async.commit_group;");
    };
    auto load_v = [&](int jt) {
        const int j0 = jt * 64;
        const uint32_t base = vb[jt & 1];
        for (int i = tid; i < 2048; i += 256) {
            const int r  = i >> 4;
            const int c4 = (i & 15) << 2;
            cp16(base + (uint32_t)(r * V_PITCH + c4) * 4u,
                 Vg + (size_t)r * SEQ + j0 + c4);
        }
        asm volatile("cp.async.commit_group;");
    };

    // ---- prologue: stage Q (128x128) across K0+K1, hoist fragments ----
    for (int i = tid; i < 4096; i += 256) {
        const int r  = i >> 5;
        const int c4 = (i & 31) << 2;
        cp16(kb[0] + (uint32_t)(r * K_PITCH + c4) * 4u, Qg + (size_t)r * HEADDIM + c4);
    }
    asm volatile("cp.async.commit_group;");
    asm volatile("cp.async.wait_group 0;");
    __syncthreads();

    uint32_t qf[16][4];
    #pragma unroll
    for (int ks = 0; ks < 16; ks++)
        ldsm_x4(qf[ks], kb[0] + a_lane_k + (uint32_t)(ks * 8 * 4));
    __syncthreads();

    load_k(0);
    load_v(0);

    float m0 = -3.0e38f, m1 = -3.0e38f, l0 = 0.0f, l1 = 0.0f;
    float o[16][4];
    #pragma unroll
    for (int nt = 0; nt < 16; nt++)
        #pragma unroll
        for (int c = 0; c < 4; c++) o[nt][c] = 0.0f;

    for (int jt = 0; jt < nj; jt++) {
        asm volatile("cp.async.wait_group 1;");   // K(jt) arrived (V(jt) may pend)
        __syncthreads();                          // all warps done with old buffers

        // ---- S = Q K^T from Kbuf[jt&1] ----
        float s_[8][4];
        #pragma unroll
        for (int t = 0; t < 8; t++)
            #pragma unroll
            for (int c = 0; c < 4; c++) s_[t][c] = 0.0f;

        const uint32_t kbase = kb[jt & 1] + b_lane_k;
        #pragma unroll
        for (int ks = 0; ks < 16; ks++) {
            const uint32_t k0b = (uint32_t)(ks * 8 * 4);
            #pragma unroll
            for (int p = 0; p < 4; p++) {
                uint32_t bt[4];
                ldsm_x4(bt, kbase + (uint32_t)(p * 16 * K_PITCH * 4) + k0b);
                mma_tf32(s_[2 * p],     qf[ks], &bt[0]);
                mma_tf32(s_[2 * p + 1], qf[ks], &bt[2]);
            }
        }

        if (jt + 1 < nj) load_k(jt + 1);          // hidden behind softmax + PV
        else             asm volatile("cp.async.commit_group;");

        if (jt >= nj - 2) {                       // causal mask (last two tiles)
            const int rrel  = wid * 16 + lq;
            const int crel0 = (jt - (nj - 2)) * 64;
            #pragma unroll
            for (int t = 0; t < 8; t++) {
                const int c0 = crel0 + t * 8 + 2 * lr;
                if (c0     > rrel)     s_[t][0] = -3.0e38f;
                if (c0 + 1 > rrel)     s_[t][1] = -3.0e38f;
                if (c0     > rrel + 8) s_[t][2] = -3.0e38f;
                if (c0 + 1 > rrel + 8) s_[t][3] = -3.0e38f;
            }
        }

        // ---- online softmax ----
        float mx0 = -3.0e38f, mx1 = -3.0e38f;
        #pragma unroll
        for (int t = 0; t < 8; t++) {
            mx0 = fmaxf(mx0, fmaxf(s_[t][0], s_[t][1]));
            mx1 = fmaxf(mx1, fmaxf(s_[t][2], s_[t][3]));
        }
        mx0 = fmaxf(mx0, __shfl_xor_sync(0xffffffffu, mx0, 1));
        mx0 = fmaxf(mx0, __shfl_xor_sync(0xffffffffu, mx0, 2));
        mx1 = fmaxf(mx1, __shfl_xor_sync(0xffffffffu, mx1, 1));
        mx1 = fmaxf(mx1, __shfl_xor_sync(0xffffffffu, mx1, 2));

        const float mn0 = fmaxf(m0, mx0);
        const float mn1 = fmaxf(m1, mx1);
        const float al0 = __expf(m0 - mn0);
        const float al1 = __expf(m1 - mn1);
        float rs0 = 0.0f, rs1 = 0.0f;
        #pragma unroll
        for (int t = 0; t < 8; t++) {
            s_[t][0] = __expf(s_[t][0] - mn0); rs0 += s_[t][0];
            s_[t][1] = __expf(s_[t][1] - mn0); rs0 += s_[t][1];
            s_[t][2] = __expf(s_[t][2] - mn1); rs1 += s_[t][2];
            s_[t][3] = __expf(s_[t][3] - mn1); rs1 += s_[t][3];
        }
        rs0 += __shfl_xor_sync(0xffffffffu, rs0, 1);
        rs0 += __shfl_xor_sync(0xffffffffu, rs0, 2);
        rs1 += __shfl_xor_sync(0xffffffffu, rs1, 1);
        rs1 += __shfl_xor_sync(0xffffffffu, rs1, 2);
        l0 = l0 * al0 + rs0;  m0 = mn0;
        l1 = l1 * al1 + rs1;  m1 = mn1;
        #pragma unroll
        for (int nt = 0; nt < 16; nt++) {
            o[nt][0] *= al0; o[nt][1] *= al0;
            o[nt][2] *= al1; o[nt][3] *= al1;
        }

        // ---- V(jt) must be resident before PV ----
        asm volatile("cp.async.wait_group 1;");   // V(jt) done (K(jt+1) may pend)

        // ---- store P (own rows only) ----
        {
            float* p0 = Ps + (wid * 16 + lq) * P_PITCH + 2 * lr;
            float* p1 = p0 + 8 * P_PITCH;
            #pragma unroll
            for (int t = 0; t < 8; t++) {
                p0[t * 8]     = tfr(s_[t][0]);
                p0[t * 8 + 1] = tfr(s_[t][1]);
                p1[t * 8]     = tfr(s_[t][2]);
                p1[t * 8 + 1] = tfr(s_[t][3]);
            }
        }
        __syncwarp();

        // ---- O += P Vt from Vbuf[jt&1] ----
        const uint32_t vbase = vb[jt & 1] + b_lane_v;
        #pragma unroll
        for (int k0 = 0; k0 < 64; k0 += 8) {
            const uint32_t k0b = (uint32_t)(k0 * 4);
            uint32_t a[4];
            ldsm_x4(a, ps_base + a_lane_p + k0b);
            #pragma unroll
            for (int p = 0; p < 8; p++) {
                uint32_t bt[4];
                ldsm_x4(bt, vbase + (uint32_t)(p * 16 * V_PITCH * 4) + k0b);
                mma_tf32(o[2 * p],     a, &bt[0]);
                mma_tf32(o[2 * p + 1], a, &bt[2]);
            }
        }

        if (jt + 1 < nj) load_v(jt + 1);          // hidden behind next S + softmax
        else             asm volatile("cp.async.commit_group;");
    }

    // ---- epilogue ----
    const float inv0 = 1.0f / l0;
    const float inv1 = 1.0f / l1;
    const int s0 = q0 + wid * 16 + lq;
    float* O0 = g_attn + (size_t)(b * SEQ + s0) * DMODEL + h * HEADDIM + 2 * lr;
    float* O1 = O0 + (size_t)8 * DMODEL;
    #pragma unroll
    for (int nt = 0; nt < 16; nt++) {
        float2 v0 = make_float2(tfr(o[nt][0] * inv0), tfr(o[nt][1] * inv0));
        float2 v1 = make_float2(tfr(o[nt][2] * inv1), tfr(o[nt][3] * inv1));
        *(float2*)(O0 + nt * 8) = v0;
        *(float2*)(O1 + nt * 8) = v1;
    }
}

// ---------------------------------------------------------------------------
// Launch sequence
// ---------------------------------------------------------------------------
extern "C" void kernel_launch(void* const* d_in, const int* in_sizes, int n_in,
                              void* d_out, int out_size)
{
    const float* hidden = (const float*)d_in[0];
    const float* Wqkv   = (const float*)d_in[3];
    const float* out_w  = (const float*)d_in[4];
    float*       out    = (float*)d_out;

    float *qkv_p, *attn_p, *hid_p, *wq_p, *wo_p;
    cudaGetSymbolAddress((void**)&qkv_p,  g_qkv);
    cudaGetSymbolAddress((void**)&attn_p, g_attn);
    cudaGetSymbolAddress((void**)&hid_p,  g_hid_r);
    cudaGetSymbolAddress((void**)&wq_p,   g_wq_r);
    cudaGetSymbolAddress((void**)&wo_p,   g_wo_r);

    cudaFuncSetAttribute(gemm_tf32<true>,
                         cudaFuncAttributeMaxDynamicSharedMemorySize, GEMM_SMEM_BYTES);
    cudaFuncSetAttribute(gemm_tf32<false>,
                         cudaFuncAttributeMaxDynamicSharedMemorySize, GEMM_SMEM_BYTES);
    cudaFuncSetAttribute(attn_kernel,
                         cudaFuncAttributeMaxDynamicSharedMemorySize, ATTN_SMEM_BYTES);

    // 0) pre-round operands to tf32
    round_tf32_kernel<<<1184, 256>>>((const float4*)hidden, (float4*)hid_p,
                                     TOKENS * DMODEL / 4);
    round_tf32_kernel<<<1184, 256>>>((const float4*)Wqkv, (float4*)wq_p,
                                     QKV_N * DMODEL / 4);
    round_tf32_kernel<<<1184, 256>>>((const float4*)out_w, (float4*)wo_p,
                                     DMODEL * DMODEL / 4);

    // 1) QKV projection with clip
    gemm_tf32<true><<<dim3(QKV_N / BN, TOKENS / BM), 256, GEMM_SMEM_BYTES>>>(
        hid_p, wq_p, qkv_p, TOKENS, QKV_N, DMODEL);

    // 2) RoPE + layouts (tf32-rounded outputs)
    rope_kernel<<<TOKENS, 256>>>();

    // 3) tensor-core causal flash attention (Bq=128, double-buffered K/V)
    attn_kernel<<<dim3(SEQ / 128, NHEADS, BATCH), 256, ATTN_SMEM_BYTES>>>();

    // 4) output projection
    gemm_tf32<false><<<dim3(DMODEL / BN, TOKENS / BM), 256, GEMM_SMEM_BYTES>>>(
        attn_p, wo_p, out, TOKENS, DMODEL, DMODEL);
}

// round 11
// speedup vs baseline: 1.8443x; 1.7931x over previous
#include <cuda_runtime.h>
#include <cuda_fp16.h>
#include <math.h>
#include <stdint.h>

// ---------------------------------------------------------------------------
// Problem constants
// ---------------------------------------------------------------------------
#define BATCH     2
#define SEQ       2048
#define DMODEL    4096
#define NHEADS    32
#define KVHEADS   8
#define HEADDIM   128
#define QKV_N     (DMODEL + 2 * KVHEADS * HEADDIM)   // 6144
#define TOKENS    (BATCH * SEQ)                      // 4096
#define CLIP_V    8.0f
#define INV_SQRT_D 0.08838834764831845f

// ---------------------------------------------------------------------------
// Scratch (device globals; no dynamic allocation allowed) — fp16 operands
// ---------------------------------------------------------------------------
__device__ __half g_qkv [(size_t)TOKENS * QKV_N];                  // [b,s,6144] clipped
__device__ __half g_q   [(size_t)BATCH * NHEADS  * SEQ * HEADDIM]; // [b,h,s,d] prescaled
__device__ __half g_k   [(size_t)BATCH * KVHEADS * SEQ * HEADDIM]; // [b,hk,s,d]
__device__ __half g_vt  [(size_t)BATCH * KVHEADS * HEADDIM * SEQ]; // [b,hk,d,s]
__device__ __half g_attn[(size_t)TOKENS * DMODEL];                 // [b,s,4096]
__device__ __half g_hid [(size_t)TOKENS * DMODEL];
__device__ __half g_wq  [(size_t)QKV_N  * DMODEL];
__device__ __half g_wo  [(size_t)DMODEL * DMODEL];

// ---------------------------------------------------------------------------
// helpers
// ---------------------------------------------------------------------------
__device__ __forceinline__ void mma_f16(float* c, const uint32_t* a, const uint32_t* b) {
    asm volatile(
        "mma.sync.aligned.m16n8k16.row.col.f32.f16.f16.f32 "
        "{%0,%1,%2,%3}, {%4,%5,%6,%7}, {%8,%9}, {%0,%1,%2,%3};"
        : "+f"(c[0]), "+f"(c[1]), "+f"(c[2]), "+f"(c[3])
        : "r"(a[0]), "r"(a[1]), "r"(a[2]), "r"(a[3]), "r"(b[0]), "r"(b[1]));
}
__device__ __forceinline__ void cp16(uint32_t s, const void* g) {
    asm volatile("cp.async.cg.shared.global [%0], [%1], 16;" :: "r"(s), "l"(g));
}
__device__ __forceinline__ void ldsm_x4(uint32_t* r, uint32_t addr) {
    asm volatile("ldmatrix.sync.aligned.m8n8.x4.shared.b16 {%0,%1,%2,%3}, [%4];"
                 : "=r"(r[0]), "=r"(r[1]), "=r"(r[2]), "=r"(r[3]) : "r"(addr));
}

// ---------------------------------------------------------------------------
// elementwise f32 -> fp16 round (float4 grid-stride)
// ---------------------------------------------------------------------------
__global__ __launch_bounds__(256)
void round_h_kernel(const float4* __restrict__ in, half2* __restrict__ out, int n4)
{
    for (int i = blockIdx.x * blockDim.x + threadIdx.x; i < n4; i += gridDim.x * blockDim.x) {
        float4 v = in[i];
        out[2 * i]     = __floats2half2_rn(v.x, v.y);
        out[2 * i + 1] = __floats2half2_rn(v.z, v.w);
    }
}

// ---------------------------------------------------------------------------
// FP16 tensor-core GEMM:  C[M,N] = A[M,K] * B[N,K]^T  (A,B pre-rounded half)
// 128x128x64 block tile, 8 warps (2x4), warp tile 64x32, m16n8k16 mma.
// 3-stage cp.async pipeline (36,864 B/stage = 110,592 B total -> 2 CTAs/SM).
// smem row pitch 72 halves (144B: 16B-aligned, 36-word stride -> distinct banks).
// OUT_HALF: write clipped half2 (QKV).  else: f32 staged float4 stores (out-proj).
// ---------------------------------------------------------------------------
#define BM 128
#define BN 128
#define HBK 64
#define HKP 72
#define STAGE_HALVES (BM * HKP + BN * HKP)            // 18,432 halves
#define GEMM_SMEM_BYTES (3 * STAGE_HALVES * 2)        // 110,592
#define EP_PITCH 36

template <bool DO_CLIP, bool OUT_HALF>
__global__ __launch_bounds__(256, 2)
void gemm_f16(const __half* __restrict__ A, const __half* __restrict__ B,
              void* __restrict__ Cv, int M, int N, int K)
{
    extern __shared__ char smc[];
    const uint32_t smem_base = (uint32_t)__cvta_generic_to_shared(smc);

    const int tid = threadIdx.x;
    const int ln  = tid & 31;
    const int wid = tid >> 5;
    const int wm  = wid >> 2;
    const int wn  = wid & 3;
    const int m0  = blockIdx.y * BM;
    const int n0  = blockIdx.x * BN;
    const int lq  = ln >> 2;
    const int lr  = ln & 3;

    // byte offsets (pitch in halves * 2)
    const uint32_t a_lane = (uint32_t)(((wm * 64 + (ln & 15)) * HKP + (ln >> 4) * 8) * 2);
    const uint32_t b_lane = (uint32_t)(((wn * 32 + (ln >> 4) * 8 + (ln & 7)) * HKP
                                        + ((ln >> 3) & 1) * 8) * 2);

    const __half* Abase = A + (size_t)m0 * K;
    const __half* Bbase = B + (size_t)n0 * K;

    auto load_stage = [&](int kt, int s) {
        const __half* Ag = Abase + kt * HBK;
        const __half* Bg = Bbase + kt * HBK;
        const uint32_t sa = smem_base + (uint32_t)(s * STAGE_HALVES) * 2u;
        const uint32_t sb = sa + BM * HKP * 2u;
        #pragma unroll
        for (int r = 0; r < 4; r++) {                 // 1024 A chunks + 1024 B
            const int i   = r * 256 + tid;
            const int row = i >> 3;
            const int kc  = (i & 7) << 3;             // halves
            cp16(sa + (uint32_t)(row * HKP + kc) * 2u, Ag + (size_t)row * K + kc);
            cp16(sb + (uint32_t)(row * HKP + kc) * 2u, Bg + (size_t)row * K + kc);
        }
        asm volatile("cp.async.commit_group;");
    };

    load_stage(0, 0);
    load_stage(1, 1);

    float acc[4][4][4];
    #pragma unroll
    for (int a = 0; a < 4; a++)
        #pragma unroll
        for (int b = 0; b < 4; b++)
            #pragma unroll
            for (int c = 0; c < 4; c++) acc[a][b][c] = 0.0f;

    const int nk = K / HBK;
    for (int kt = 0; kt < nk; kt++) {
        asm volatile("cp.async.wait_group 1;");
        __syncthreads();

        if (kt + 2 < nk) load_stage(kt + 2, (kt + 2) % 3);
        else             asm volatile("cp.async.commit_group;");

        const uint32_t st = smem_base + (uint32_t)((kt % 3) * STAGE_HALVES) * 2u;
        const uint32_t aa = st + a_lane;
        const uint32_t bb = st + BM * HKP * 2u + b_lane;

        #pragma unroll
        for (int ks = 0; ks < 4; ks++) {              // 4 k-steps of 16
            const uint32_t k0b = (uint32_t)(ks * 32); // 16 halves = 32B
            uint32_t af[4][4], bf[2][4];
            #pragma unroll
            for (int mt = 0; mt < 4; mt++)
                ldsm_x4(af[mt], aa + (uint32_t)(mt * 16 * HKP * 2) + k0b);
            ldsm_x4(bf[0], bb + k0b);                              // nt 0,1
            ldsm_x4(bf[1], bb + (uint32_t)(16 * HKP * 2) + k0b);   // nt 2,3
            #pragma unroll
            for (int mt = 0; mt < 4; mt++) {
                mma_f16(acc[mt][0], af[mt], &bf[0][0]);
                mma_f16(acc[mt][1], af[mt], &bf[0][2]);
                mma_f16(acc[mt][2], af[mt], &bf[1][0]);
                mma_f16(acc[mt][3], af[mt], &bf[1][2]);
            }
        }
    }
    __syncthreads();

    if (OUT_HALF) {
        // direct half2 stores (clipped): 4B per store, quad-contiguous 16B
        __half* C = (__half*)Cv;
        #pragma unroll
        for (int mt = 0; mt < 4; mt++) {
            #pragma unroll
            for (int nt = 0; nt < 4; nt++) {
                const int row = m0 + wm * 64 + mt * 16 + lq;
                const int col = n0 + wn * 32 + nt * 8 + lr * 2;
                float x0 = acc[mt][nt][0], x1 = acc[mt][nt][1];
                float x2 = acc[mt][nt][2], x3 = acc[mt][nt][3];
                if (DO_CLIP) {
                    x0 = fminf(fmaxf(x0, -CLIP_V), CLIP_V);
                    x1 = fminf(fmaxf(x1, -CLIP_V), CLIP_V);
                    x2 = fminf(fmaxf(x2, -CLIP_V), CLIP_V);
                    x3 = fminf(fmaxf(x3, -CLIP_V), CLIP_V);
                }
                *(half2*)(C + (size_t)row * N + col)       = __floats2half2_rn(x0, x1);
                *(half2*)(C + (size_t)(row + 8) * N + col) = __floats2half2_rn(x2, x3);
            }
        }
    } else {
        // f32 output staged through smem for coalesced float4 stores
        float* C  = (float*)Cv;
        float* ep = (float*)smc + wid * (64 * EP_PITCH);
        #pragma unroll
        for (int mt = 0; mt < 4; mt++) {
            __syncwarp();
            #pragma unroll
            for (int nt = 0; nt < 4; nt++) {
                float* p0 = ep + (lq)     * EP_PITCH + nt * 8 + lr * 2;
                float* p1 = ep + (lq + 8) * EP_PITCH + nt * 8 + lr * 2;
                p0[0] = acc[mt][nt][0]; p0[1] = acc[mt][nt][1];
                p1[0] = acc[mt][nt][2]; p1[1] = acc[mt][nt][3];
            }
            __syncwarp();
            #pragma unroll
            for (int rr = 0; rr < 4; rr++) {
                const int row = rr * 4 + (ln >> 3);
                const int c4  = (ln & 7) * 4;
                float4 v = *(float4*)&ep[row * EP_PITCH + c4];
                *(float4*)(C + (size_t)(m0 + wm * 64 + mt * 16 + row) * N
                             + n0 + wn * 32 + c4) = v;
            }
        }
    }
}

// ---------------------------------------------------------------------------
// RoPE + layout: g_qkv(half) -> g_q/g_k (half, [.,s,d]) and g_vt (half, [.,d,s])
// ---------------------------------------------------------------------------
__global__ __launch_bounds__(256)
void rope_kernel()
{
    const int token = blockIdx.x;
    const int b    = token / SEQ;
    const int spos = token - b * SEQ;
    const __half* row = g_qkv + (size_t)token * QKV_N;
    const float posf = (float)spos;

    for (int idx = threadIdx.x; idx < (NHEADS + KVHEADS) * 64; idx += 256) {
        const int h = idx >> 6;
        const int j = idx & 63;
        const float freq = __powf(500000.0f, -(float)j * (1.0f / 64.0f));
        float s, c;
        sincosf(posf * freq, &s, &c);

        const float x1 = __half2float(row[h * HEADDIM + j]);
        const float x2 = __half2float(row[h * HEADDIM + 64 + j]);
        const float y1 = x1 * c - x2 * s;
        const float y2 = x2 * c + x1 * s;

        if (h < NHEADS) {
            __half* q = g_q + ((size_t)(b * NHEADS + h) * SEQ + spos) * HEADDIM;
            q[j]      = __float2half_rn(y1 * INV_SQRT_D);
            q[j + 64] = __float2half_rn(y2 * INV_SQRT_D);
        } else {
            __half* k = g_k + ((size_t)(b * KVHEADS + (h - NHEADS)) * SEQ + spos) * HEADDIM;
            k[j]      = __float2half_rn(y1);
            k[j + 64] = __float2half_rn(y2);
        }
    }

    const __half* vrow = row + DMODEL + KVHEADS * HEADDIM;
    for (int idx = threadIdx.x; idx < KVHEADS * HEADDIM; idx += 256) {
        const int hk = idx >> 7;
        const int d  = idx & 127;
        g_vt[((size_t)(b * KVHEADS + hk) * HEADDIM + d) * SEQ + spos] = vrow[hk * HEADDIM + d];
    }
}

// ---------------------------------------------------------------------------
// FP16 tensor-core causal flash attention — Bq=128, 8 warps, Q in registers,
// double-buffered K and V.  smem: K0,K1[64][136] V0,V1[128][72] P[128][72]
// = 90,112 B.  Q staged across K0+K1 in the prologue.
// ---------------------------------------------------------------------------
#define AK_PITCH 136   // halves (272B rows)
#define AV_PITCH 72    // halves (144B rows)
#define AP_PITCH 72
#define AK_BYTES (64 * AK_PITCH * 2)    // 17,408
#define AV_BYTES (128 * AV_PITCH * 2)   // 18,432
#define AP_BYTES (128 * AP_PITCH * 2)   // 18,432
#define ATTN_SMEM_BYTES (2 * AK_BYTES + 2 * AV_BYTES + AP_BYTES)  // 90,112

__global__ __launch_bounds__(256, 1)
void attn_kernel()
{
    extern __shared__ char smc[];
    const uint32_t smem_base = (uint32_t)__cvta_generic_to_shared(smc);
    const uint32_t kb[2] = { smem_base, smem_base + AK_BYTES };
    const uint32_t vb[2] = { smem_base + 2 * AK_BYTES,
                             smem_base + 2 * AK_BYTES + AV_BYTES };
    const uint32_t ps_base = smem_base + 2 * AK_BYTES + 2 * AV_BYTES;
    __half* Ph = (__half*)(smc + 2 * AK_BYTES + 2 * AV_BYTES);

    const int qtile = (SEQ / 128 - 1) - blockIdx.x;   // heavy tiles first
    const int h  = blockIdx.y;
    const int b  = blockIdx.z;
    const int hk = h >> 2;
    const int q0 = qtile * 128;
    const int nj = 2 * qtile + 2;                     // 64-wide k-tiles

    const int tid = threadIdx.x;
    const int ln  = tid & 31;
    const int wid = tid >> 5;
    const int lq  = ln >> 2;
    const int lr  = ln & 3;

    const uint32_t a_lane_k = (uint32_t)(((wid * 16 + (ln & 15)) * AK_PITCH
                                          + (ln >> 4) * 8) * 2);
    const uint32_t a_lane_p = (uint32_t)(((wid * 16 + (ln & 15)) * AP_PITCH
                                          + (ln >> 4) * 8) * 2);
    const uint32_t b_lane_k = (uint32_t)((((ln >> 4) * 8 + (ln & 7)) * AK_PITCH
                                          + ((ln >> 3) & 1) * 8) * 2);
    const uint32_t b_lane_v = (uint32_t)((((ln >> 4) * 8 + (ln & 7)) * AV_PITCH
                                          + ((ln >> 3) & 1) * 8) * 2);

    const __half* Qg = g_q  + ((size_t)(b * NHEADS  + h)  * SEQ + q0) * HEADDIM;
    const __half* Kg = g_k  + ((size_t)(b * KVHEADS + hk) * SEQ) * HEADDIM;
    const __half* Vg = g_vt + ((size_t)(b * KVHEADS + hk) * HEADDIM) * SEQ;

    auto load_k = [&](int jt) {
        const int j0 = jt * 64;
        const uint32_t base = kb[jt & 1];
        for (int i = tid; i < 1024; i += 256) {       // 64 rows x 16 chunks
            const int r  = i >> 4;
            const int c8 = (i & 15) << 3;
            cp16(base + (uint32_t)(r * AK_PITCH + c8) * 2u,
                 Kg + (size_t)(j0 + r) * HEADDIM + c8);
        }
        asm volatile("cp.async.commit_group;");
    };
    auto load_v = [&](int jt) {
        const int j0 = jt * 64;
        const uint32_t base = vb[jt & 1];
        for (int i = tid; i < 1024; i += 256) {       // 128 rows x 8 chunks
            const int r  = i >> 3;
            const int c8 = (i & 7) << 3;
            cp16(base + (uint32_t)(r * AV_PITCH + c8) * 2u,
                 Vg + (size_t)r * SEQ + j0 + c8);
        }
        asm volatile("cp.async.commit_group;");
    };

    // ---- prologue: stage Q (128x128 halves) across K0+K1, hoist fragments ----
    for (int i = tid; i < 2048; i += 256) {
        const int r  = i >> 4;
        const int c8 = (i & 15) << 3;
        cp16(kb[0] + (uint32_t)(r * AK_PITCH + c8) * 2u, Qg + (size_t)r * HEADDIM + c8);
    }
    asm volatile("cp.async.commit_group;");
    asm volatile("cp.async.wait_group 0;");
    __syncthreads();

    uint32_t qf[8][4];
    #pragma unroll
    for (int ks = 0; ks < 8; ks++)
        ldsm_x4(qf[ks], kb[0] + a_lane_k + (uint32_t)(ks * 32));
    __syncthreads();

    load_k(0);
    load_v(0);

    float m0 = -3.0e38f, m1 = -3.0e38f, l0 = 0.0f, l1 = 0.0f;
    float o[16][4];
    #pragma unroll
    for (int nt = 0; nt < 16; nt++)
        #pragma unroll
        for (int c = 0; c < 4; c++) o[nt][c] = 0.0f;

    for (int jt = 0; jt < nj; jt++) {
        asm volatile("cp.async.wait_group 1;");   // K(jt) arrived
        __syncthreads();

        // ---- S = Q K^T ----
        float s_[8][4];
        #pragma unroll
        for (int t = 0; t < 8; t++)
            #pragma unroll
            for (int c = 0; c < 4; c++) s_[t][c] = 0.0f;

        const uint32_t kbase = kb[jt & 1] + b_lane_k;
        #pragma unroll
        for (int ks = 0; ks < 8; ks++) {
            const uint32_t k0b = (uint32_t)(ks * 32);
            #pragma unroll
            for (int p = 0; p < 4; p++) {
                uint32_t bt[4];
                ldsm_x4(bt, kbase + (uint32_t)(p * 16 * AK_PITCH * 2) + k0b);
                mma_f16(s_[2 * p],     qf[ks], &bt[0]);
                mma_f16(s_[2 * p + 1], qf[ks], &bt[2]);
            }
        }

        if (jt + 1 < nj) load_k(jt + 1);
        else             asm volatile("cp.async.commit_group;");

        if (jt >= nj - 2) {                       // causal mask (last two tiles)
            const int rrel  = wid * 16 + lq;
            const int crel0 = (jt - (nj - 2)) * 64;
            #pragma unroll
            for (int t = 0; t < 8; t++) {
                const int c0 = crel0 + t * 8 + 2 * lr;
                if (c0     > rrel)     s_[t][0] = -3.0e38f;
                if (c0 + 1 > rrel)     s_[t][1] = -3.0e38f;
                if (c0     > rrel + 8) s_[t][2] = -3.0e38f;
                if (c0 + 1 > rrel + 8) s_[t][3] = -3.0e38f;
            }
        }

        // ---- online softmax ----
        float mx0 = -3.0e38f, mx1 = -3.0e38f;
        #pragma unroll
        for (int t = 0; t < 8; t++) {
            mx0 = fmaxf(mx0, fmaxf(s_[t][0], s_[t][1]));
            mx1 = fmaxf(mx1, fmaxf(s_[t][2], s_[t][3]));
        }
        mx0 = fmaxf(mx0, __shfl_xor_sync(0xffffffffu, mx0, 1));
        mx0 = fmaxf(mx0, __shfl_xor_sync(0xffffffffu, mx0, 2));
        mx1 = fmaxf(mx1, __shfl_xor_sync(0xffffffffu, mx1, 1));
        mx1 = fmaxf(mx1, __shfl_xor_sync(0xffffffffu, mx1, 2));

        const float mn0 = fmaxf(m0, mx0);
        const float mn1 = fmaxf(m1, mx1);
        const float al0 = __expf(m0 - mn0);
        const float al1 = __expf(m1 - mn1);
        float rs0 = 0.0f, rs1 = 0.0f;
        #pragma unroll
        for (int t = 0; t < 8; t++) {
            s_[t][0] = __expf(s_[t][0] - mn0); rs0 += s_[t][0];
            s_[t][1] = __expf(s_[t][1] - mn0); rs0 += s_[t][1];
            s_[t][2] = __expf(s_[t][2] - mn1); rs1 += s_[t][2];
            s_[t][3] = __expf(s_[t][3] - mn1); rs1 += s_[t][3];
        }
        rs0 += __shfl_xor_sync(0xffffffffu, rs0, 1);
        rs0 += __shfl_xor_sync(0xffffffffu, rs0, 2);
        rs1 += __shfl_xor_sync(0xffffffffu, rs1, 1);
        rs1 += __shfl_xor_sync(0xffffffffu, rs1, 2);
        l0 = l0 * al0 + rs0;  m0 = mn0;
        l1 = l1 * al1 + rs1;  m1 = mn1;
        #pragma unroll
        for (int nt = 0; nt < 16; nt++) {
            o[nt][0] *= al0; o[nt][1] *= al0;
            o[nt][2] *= al1; o[nt][3] *= al1;
        }

        asm volatile("cp.async.wait_group 1;");   // V(jt) resident

        // ---- store P as half (own rows only) ----
        {
            __half* p0 = Ph + (wid * 16 + lq) * AP_PITCH + 2 * lr;
            __half* p1 = p0 + 8 * AP_PITCH;
            #pragma unroll
            for (int t = 0; t < 8; t++) {
                *(half2*)(p0 + t * 8) = __floats2half2_rn(s_[t][0], s_[t][1]);
                *(half2*)(p1 + t * 8) = __floats2half2_rn(s_[t][2], s_[t][3]);
            }
        }
        __syncwarp();

        // ---- O += P Vt ----
        const uint32_t vbase = vb[jt & 1] + b_lane_v;
        #pragma unroll
        for (int ks = 0; ks < 4; ks++) {
            const uint32_t k0b = (uint32_t)(ks * 32);
            uint32_t a[4];
            ldsm_x4(a, ps_base + a_lane_p + k0b);
            #pragma unroll
            for (int p = 0; p < 8; p++) {
                uint32_t bt[4];
                ldsm_x4(bt, vbase + (uint32_t)(p * 16 * AV_PITCH * 2) + k0b);
                mma_f16(o[2 * p],     a, &bt[0]);
                mma_f16(o[2 * p + 1], a, &bt[2]);
            }
        }

        if (jt + 1 < nj) load_v(jt + 1);
        else             asm volatile("cp.async.commit_group;");
    }

    // ---- epilogue: normalize, write half2 to g_attn ----
    const float inv0 = 1.0f / l0;
    const float inv1 = 1.0f / l1;
    const int s0 = q0 + wid * 16 + lq;
    __half* O0 = g_attn + (size_t)(b * SEQ + s0) * DMODEL + h * HEADDIM + 2 * lr;
    __half* O1 = O0 + (size_t)8 * DMODEL;
    #pragma unroll
    for (int nt = 0; nt < 16; nt++) {
        *(half2*)(O0 + nt * 8) = __floats2half2_rn(o[nt][0] * inv0, o[nt][1] * inv0);
        *(half2*)(O1 + nt * 8) = __floats2half2_rn(o[nt][2] * inv1, o[nt][3] * inv1);
    }
}

// ---------------------------------------------------------------------------
// Launch sequence
// Inputs: 0=hidden_states f32, 1=position_ids i64 (arange), 2=attention_mask
//         (causal), 3=Wqkv_w f32, 4=out_w f32
// ---------------------------------------------------------------------------
extern "C" void kernel_launch(void* const* d_in, const int* in_sizes, int n_in,
                              void* d_out, int out_size)
{
    const float* hidden = (const float*)d_in[0];
    const float* Wqkv   = (const float*)d_in[3];
    const float* out_w  = (const float*)d_in[4];
    float*       out    = (float*)d_out;

    __half *qkv_p, *attn_p, *hid_p, *wq_p, *wo_p;
    cudaGetSymbolAddress((void**)&qkv_p,  g_qkv);
    cudaGetSymbolAddress((void**)&attn_p, g_attn);
    cudaGetSymbolAddress((void**)&hid_p,  g_hid);
    cudaGetSymbolAddress((void**)&wq_p,   g_wq);
    cudaGetSymbolAddress((void**)&wo_p,   g_wo);

    cudaFuncSetAttribute((const void*)gemm_f16<true, true>,
                         cudaFuncAttributeMaxDynamicSharedMemorySize, GEMM_SMEM_BYTES);
    cudaFuncSetAttribute((const void*)gemm_f16<false, false>,
                         cudaFuncAttributeMaxDynamicSharedMemorySize, GEMM_SMEM_BYTES);
    cudaFuncSetAttribute((const void*)attn_kernel,
                         cudaFuncAttributeMaxDynamicSharedMemorySize, ATTN_SMEM_BYTES);

    // 0) pre-round operands to fp16
    round_h_kernel<<<1184, 256>>>((const float4*)hidden, (half2*)hid_p,
                                  TOKENS * DMODEL / 4);
    round_h_kernel<<<1184, 256>>>((const float4*)Wqkv, (half2*)wq_p,
                                  QKV_N * DMODEL / 4);
    round_h_kernel<<<1184, 256>>>((const float4*)out_w, (half2*)wo_p,
                                  DMODEL * DMODEL / 4);

    // 1) QKV projection with clip (half output)
    gemm_f16<true, true><<<dim3(QKV_N / BN, TOKENS / BM), 256, GEMM_SMEM_BYTES>>>(
        hid_p, wq_p, qkv_p, TOKENS, QKV_N, DMODEL);

    // 2) RoPE + layouts (fp16 outputs)
    rope_kernel<<<TOKENS, 256>>>();

    // 3) fp16 tensor-core causal flash attention (Bq=128, double-buffered K/V)
    attn_kernel<<<dim3(SEQ / 128, NHEADS, BATCH), 256, ATTN_SMEM_BYTES>>>();

    // 4) output projection (f32 output)
    gemm_f16<false, false><<<dim3(DMODEL / BN, TOKENS / BM), 256, GEMM_SMEM_BYTES>>>(
        attn_p, wo_p, out, TOKENS, DMODEL, DMODEL);
}